// round 1
// baseline (speedup 1.0000x reference)
#include <cuda_runtime.h>
#include <math.h>

// ---------------------------------------------------------------------------
// CIE-Net: 3x ci_conv on two graphs + sinkhorn cross-attention + final sinkhorn
// B=8, N=64, H=1024, Ein=1. Edge chain is pointwise in (b,i,j) and only ever
// consumed at positions where A[b,i,j]!=0 -> compact edges to nnz rows.
// ---------------------------------------------------------------------------

#define Bb   8
#define Nn   64
#define Hh   1024
#define BN   512                 // B*N
#define MAXP 32768               // B*N*N (upper bound on nnz)
#define NEGV -1e30f

// ------------------------------- scratch (device globals; no allocs) --------
__device__ float g_E[4][(size_t)MAXP * Hh];     // [graph][ping/pong] edge rows (pre-relu)
__device__ float g_emb[4][(size_t)BN * Hh];     // [graph][ping/pong] node embeddings
__device__ float g_nodex[(size_t)BN * Hh];
__device__ float g_nodesx[(size_t)BN * Hh];
__device__ float g_t[(size_t)BN * Hh];
__device__ float g_u[2][(size_t)BN * Hh];
__device__ float g_s[Bb * Nn * Nn];
__device__ float g_ssk[Bb * Nn * Nn];
__device__ int   g_rowcnt[2][BN];
__device__ int   g_rowptr[2][BN + 1];
__device__ int   g_colj[2][MAXP];
__device__ int   g_esrc[2][MAXP];
__device__ float g_aval[2][MAXP];
__device__ int   g_cnt[2];

// ------------------------------- compaction ---------------------------------
__global__ void k_count(const float* __restrict__ A, int* __restrict__ rowcnt) {
    int b = blockIdx.x, i = threadIdx.x;
    const float* row = A + (size_t)(b * Nn + i) * Nn;
    int c = 0;
    for (int j = 0; j < Nn; j++) c += (row[j] != 0.0f);
    rowcnt[b * Nn + i] = c;
}

__global__ void k_scan(const int* __restrict__ rowcnt, int* __restrict__ rowptr,
                       int* __restrict__ cnt) {
    __shared__ int sm[BN];
    int t = threadIdx.x;
    sm[t] = rowcnt[t];
    __syncthreads();
    for (int off = 1; off < BN; off <<= 1) {
        int v = (t >= off) ? sm[t - off] : 0;
        __syncthreads();
        sm[t] += v;
        __syncthreads();
    }
    rowptr[t + 1] = sm[t];
    if (t == 0)   rowptr[0] = 0;
    if (t == BN - 1) *cnt = sm[BN - 1];
}

__global__ void k_fill(const float* __restrict__ A, const int* __restrict__ rowptr,
                       int* __restrict__ colj, int* __restrict__ esrc,
                       float* __restrict__ aval) {
    int b = blockIdx.x, i = threadIdx.x;
    int r = b * Nn + i;
    const float* row = A + (size_t)r * Nn;
    int pos = rowptr[r];
    for (int j = 0; j < Nn; j++) {
        float a = row[j];
        if (a != 0.0f) { colj[pos] = j; esrc[pos] = r * Nn + j; aval[pos] = a; pos++; }
    }
}

// ------------------- layer-0 edge outer-product (Ein=1) ---------------------
__global__ void k_edge0(const float* __restrict__ fe, const int* __restrict__ esrc,
                        const int* __restrict__ cnt, const float* __restrict__ ew,
                        const float* __restrict__ eb, float* __restrict__ E) {
    int p = blockIdx.x;
    if (p >= *cnt) return;
    float f = fe[esrc[p]];
    for (int c = threadIdx.x; c < Hh; c += 256)
        E[(size_t)p * Hh + c] = f * ew[c] + eb[c];
}

// ------------------------------- generic SGEMM ------------------------------
// C[M,N] = op(A)[M,K] @ B[K,N] (+bias) (+C if beta). op = relu if reluA.
// 64x64 tile, K-tile 16, 256 threads, 4x4 per thread. Dynamic M via Mptr.
__global__ void __launch_bounds__(256)
k_sgemm(const float* __restrict__ A, const float* __restrict__ B,
        float* __restrict__ C, int M, const int* __restrict__ Mptr,
        int K, int N, const float* __restrict__ bias, int beta, int reluA) {
    if (Mptr) M = *Mptr;
    int m0 = blockIdx.x << 6;
    if (m0 >= M) return;
    int n0 = blockIdx.y << 6;
    __shared__ float As[16][68];
    __shared__ float Bs[16][68];
    int t = threadIdx.x;
    int tx = t & 15, ty = t >> 4;
    int am = t >> 2, ak = (t & 3) << 2;   // A: float4 along K
    int bk = t >> 4, bn = (t & 15) << 2;  // B: float4 along N
    float acc[4][4];
#pragma unroll
    for (int i = 0; i < 4; i++)
#pragma unroll
        for (int j = 0; j < 4; j++) acc[i][j] = 0.f;

    for (int k0 = 0; k0 < K; k0 += 16) {
        float4 av = make_float4(0.f, 0.f, 0.f, 0.f);
        if (m0 + am < M)
            av = *(const float4*)(A + (size_t)(m0 + am) * K + k0 + ak);
        if (reluA) {
            av.x = fmaxf(av.x, 0.f); av.y = fmaxf(av.y, 0.f);
            av.z = fmaxf(av.z, 0.f); av.w = fmaxf(av.w, 0.f);
        }
        float4 bv = *(const float4*)(B + (size_t)(k0 + bk) * N + n0 + bn);
        __syncthreads();
        As[ak + 0][am] = av.x; As[ak + 1][am] = av.y;
        As[ak + 2][am] = av.z; As[ak + 3][am] = av.w;
        *(float4*)&Bs[bk][bn] = bv;
        __syncthreads();
#pragma unroll
        for (int k = 0; k < 16; k++) {
            float4 a = *(float4*)&As[k][ty << 2];
            float4 b = *(float4*)&Bs[k][tx << 2];
            acc[0][0] += a.x * b.x; acc[0][1] += a.x * b.y; acc[0][2] += a.x * b.z; acc[0][3] += a.x * b.w;
            acc[1][0] += a.y * b.x; acc[1][1] += a.y * b.y; acc[1][2] += a.y * b.z; acc[1][3] += a.y * b.w;
            acc[2][0] += a.z * b.x; acc[2][1] += a.z * b.y; acc[2][2] += a.z * b.z; acc[2][3] += a.z * b.w;
            acc[3][0] += a.w * b.x; acc[3][1] += a.w * b.y; acc[3][2] += a.w * b.z; acc[3][3] += a.w * b.w;
        }
    }
#pragma unroll
    for (int ii = 0; ii < 4; ii++) {
        int m = m0 + (ty << 2) + ii;
        if (m < M) {
#pragma unroll
            for (int jj = 0; jj < 4; jj++) {
                int n = n0 + (tx << 2) + jj;
                float v = acc[ii][jj];
                if (bias) v += bias[n];
                size_t idx = (size_t)m * N + n;
                if (beta) v += C[idx];
                C[idx] = v;
            }
        }
    }
}

// ----------------- node aggregation + relu-combine (fused) ------------------
// emb[b,i,c] = relu( sum_{p in row(b,i)} a_p * E[p,c] * nodex[b,j_p,c] ) + relu(nodesx[b,i,c])
__global__ void k_agg(const float* __restrict__ E, const int* __restrict__ rowptr,
                      const int* __restrict__ colj, const float* __restrict__ aval,
                      const float* __restrict__ ndx, const float* __restrict__ ndsx,
                      float* __restrict__ emb) {
    int r = blockIdx.x;
    int b = r >> 6;
    int c = (blockIdx.y << 8) + threadIdx.x;
    int s = rowptr[r], e = rowptr[r + 1];
    float acc = 0.f;
    for (int p = s; p < e; p++) {
        acc += aval[p] * E[(size_t)p * Hh + c] *
               ndx[(size_t)((b << 6) + colj[p]) * Hh + c];
    }
    emb[(size_t)r * Hh + c] = fmaxf(acc, 0.f) + fmaxf(ndsx[(size_t)r * Hh + c], 0.f);
}

// ------------------- batched NT GEMM: S[b] = T[b] @ E[b]^T -------------------
__global__ void __launch_bounds__(256)
k_bmm_nt(const float* __restrict__ T, const float* __restrict__ E, float* __restrict__ S) {
    int b = blockIdx.x;
    const float* Tb = T + (size_t)b * Nn * Hh;
    const float* Eb = E + (size_t)b * Nn * Hh;
    __shared__ float Ts[16][68];
    __shared__ float Es[16][68];
    int t = threadIdx.x, tx = t & 15, ty = t >> 4;
    int lr = t >> 2, lk = (t & 3) << 2;
    float acc[4][4];
#pragma unroll
    for (int i = 0; i < 4; i++)
#pragma unroll
        for (int j = 0; j < 4; j++) acc[i][j] = 0.f;

    for (int k0 = 0; k0 < Hh; k0 += 16) {
        float4 a = *(const float4*)(Tb + (size_t)lr * Hh + k0 + lk);
        float4 e = *(const float4*)(Eb + (size_t)lr * Hh + k0 + lk);
        __syncthreads();
        Ts[lk + 0][lr] = a.x; Ts[lk + 1][lr] = a.y; Ts[lk + 2][lr] = a.z; Ts[lk + 3][lr] = a.w;
        Es[lk + 0][lr] = e.x; Es[lk + 1][lr] = e.y; Es[lk + 2][lr] = e.z; Es[lk + 3][lr] = e.w;
        __syncthreads();
#pragma unroll
        for (int k = 0; k < 16; k++) {
            float4 av = *(float4*)&Ts[k][ty << 2];
            float4 bv = *(float4*)&Es[k][tx << 2];
            acc[0][0] += av.x * bv.x; acc[0][1] += av.x * bv.y; acc[0][2] += av.x * bv.z; acc[0][3] += av.x * bv.w;
            acc[1][0] += av.y * bv.x; acc[1][1] += av.y * bv.y; acc[1][2] += av.y * bv.z; acc[1][3] += av.y * bv.w;
            acc[2][0] += av.z * bv.x; acc[2][1] += av.z * bv.y; acc[2][2] += av.z * bv.z; acc[2][3] += av.z * bv.w;
            acc[3][0] += av.w * bv.x; acc[3][1] += av.w * bv.y; acc[3][2] += av.w * bv.z; acc[3][3] += av.w * bv.w;
        }
    }
#pragma unroll
    for (int ii = 0; ii < 4; ii++)
#pragma unroll
        for (int jj = 0; jj < 4; jj++)
            S[b * (Nn * Nn) + ((ty << 2) + ii) * Nn + (tx << 2) + jj] = acc[ii][jj];
}

// ---------------- U[b,i,:] = sum_j S(i,j) * Emb[b,j,:]  (trans: S(j,i)) -----
__global__ void k_su(const float* __restrict__ S, const float* __restrict__ Emb,
                     float* __restrict__ U, int trans) {
    int blk = blockIdx.x;
    int b = blk >> 6, i = blk & 63;
    __shared__ float srow[Nn];
    int t = threadIdx.x;
    if (t < Nn)
        srow[t] = trans ? S[b * (Nn * Nn) + t * Nn + i]
                        : S[b * (Nn * Nn) + i * Nn + t];
    __syncthreads();
    for (int c = t; c < Hh; c += 256) {
        float acc = 0.f;
#pragma unroll 8
        for (int j = 0; j < Nn; j++)
            acc += srow[j] * Emb[(size_t)((b << 6) + j) * Hh + c];
        U[(size_t)blk * Hh + c] = acc;
    }
}

// ------------------------------- sinkhorn ------------------------------------
__global__ void k_sinkhorn(const float* __restrict__ S, float* __restrict__ out,
                           const int* __restrict__ n1, const int* __restrict__ n2,
                           const int* __restrict__ itp) {
    __shared__ float ls[64][65];
    int b = blockIdx.x, t = threadIdx.x;
    int a1 = n1[b], a2 = n2[b];
    int tb = (a1 > a2);
    int nr = tb ? a2 : a1;
    int nc = tb ? a1 : a2;

    for (int e = t; e < 4096; e += 256) {
        int r = e >> 6, c = e & 63;
        float v = tb ? S[b * 4096 + c * 64 + r] : S[b * 4096 + r * 64 + c];
        ls[r][c] = (r < nr && c < nc) ? v / 0.05f : NEGV;
    }
    __syncthreads();

    int iters = *itp;
    int w = t >> 5, lane = t & 31;
    for (int it = 0; it < iters; it++) {
        if ((it & 1) == 0) {
            // normalize over columns within each row (axis=2)
            for (int r = w; r < 64; r += 8) {
                float x0 = ls[r][lane], x1 = ls[r][lane + 32];
                float m = fmaxf(x0, x1);
                for (int o = 16; o; o >>= 1) m = fmaxf(m, __shfl_xor_sync(0xffffffffu, m, o));
                float sm = expf(x0 - m) + expf(x1 - m);
                for (int o = 16; o; o >>= 1) sm += __shfl_xor_sync(0xffffffffu, sm, o);
                float lse = m + logf(sm);
                bool rm = (r < nr);
                ls[r][lane]      = (rm && lane < nc)        ? x0 - lse : NEGV;
                ls[r][lane + 32] = (rm && (lane + 32) < nc) ? x1 - lse : NEGV;
            }
        } else {
            // normalize over rows within each column (axis=1)
            for (int c = w; c < 64; c += 8) {
                float x0 = ls[lane][c], x1 = ls[lane + 32][c];
                float m = fmaxf(x0, x1);
                for (int o = 16; o; o >>= 1) m = fmaxf(m, __shfl_xor_sync(0xffffffffu, m, o));
                float sm = expf(x0 - m) + expf(x1 - m);
                for (int o = 16; o; o >>= 1) sm += __shfl_xor_sync(0xffffffffu, sm, o);
                float lse = m + logf(sm);
                bool cm = (c < nc);
                ls[lane][c]      = (cm && lane < nr)        ? x0 - lse : NEGV;
                ls[lane + 32][c] = (cm && (lane + 32) < nr) ? x1 - lse : NEGV;
            }
        }
        __syncthreads();
    }

    for (int e = t; e < 4096; e += 256) {
        int r = e >> 6, c = e & 63;
        float v = (r < nr && c < nc) ? expf(ls[r][c]) : 0.f;
        if (tb) out[b * 4096 + c * 64 + r] = v;
        else    out[b * 4096 + r * 64 + c] = v;
    }
}

// ------------------------------- launch --------------------------------------
extern "C" void kernel_launch(void* const* d_in, const int* in_sizes, int n_in,
                              void* d_out, int out_size) {
    (void)in_sizes; (void)n_in; (void)out_size;
    const float* fn[2]   = { (const float*)d_in[0], (const float*)d_in[1] };
    const float* Aadj[2] = { (const float*)d_in[2], (const float*)d_in[3] };
    const float* fe[2]   = { (const float*)d_in[4], (const float*)d_in[5] };
    const float* lw[3][6];
    for (int l = 0; l < 3; l++)
        for (int k = 0; k < 6; k++)
            lw[l][k] = (const float*)d_in[6 + l * 6 + k];
    const float* aff1 = (const float*)d_in[24];
    const float* aff2 = (const float*)d_in[25];
    const float* cw   = (const float*)d_in[26];
    const float* cb   = (const float*)d_in[27];
    const int*   n1   = (const int*)d_in[28];
    const int*   n2   = (const int*)d_in[29];
    const int*   itp  = (const int*)d_in[30];
    float* out = (float*)d_out;

    void* p;
    cudaGetSymbolAddress(&p, g_E);      float* E    = (float*)p;
    cudaGetSymbolAddress(&p, g_emb);    float* emb  = (float*)p;
    cudaGetSymbolAddress(&p, g_nodex);  float* ndx  = (float*)p;
    cudaGetSymbolAddress(&p, g_nodesx); float* ndsx = (float*)p;
    cudaGetSymbolAddress(&p, g_t);      float* tbuf = (float*)p;
    cudaGetSymbolAddress(&p, g_u);      float* ubuf = (float*)p;
    cudaGetSymbolAddress(&p, g_s);      float* sraw = (float*)p;
    cudaGetSymbolAddress(&p, g_ssk);    float* ssk  = (float*)p;
    cudaGetSymbolAddress(&p, g_rowcnt); int* rowcnt = (int*)p;
    cudaGetSymbolAddress(&p, g_rowptr); int* rowptr = (int*)p;
    cudaGetSymbolAddress(&p, g_colj);   int* colj   = (int*)p;
    cudaGetSymbolAddress(&p, g_esrc);   int* esrc   = (int*)p;
    cudaGetSymbolAddress(&p, g_aval);   float* aval = (float*)p;
    cudaGetSymbolAddress(&p, g_cnt);    int* cnt    = (int*)p;

    const size_t ESZ = (size_t)MAXP * Hh;
    const size_t MSZ = (size_t)BN * Hh;
#define EP(g, pp) (E + ((size_t)(g) * 2 + (pp)) * ESZ)
#define MP(g, pp) (emb + ((size_t)(g) * 2 + (pp)) * MSZ)

    dim3 gN(8, 16);     // M=512 tiles of 64 x N=1024/64
    dim3 gE(512, 16);   // M up to 32768 (dynamic)
    dim3 gA(512, 4);    // agg: row x channel-chunks

    // compaction + layer-0 edge features (pre-relu)
    for (int g = 0; g < 2; g++) {
        k_count<<<8, 64>>>(Aadj[g], rowcnt + g * BN);
        k_scan<<<1, BN>>>(rowcnt + g * BN, rowptr + g * (BN + 1), cnt + g);
        k_fill<<<8, 64>>>(Aadj[g], rowptr + g * (BN + 1), colj + g * MAXP,
                          esrc + g * MAXP, aval + g * MAXP);
        k_edge0<<<MAXP, 256>>>(fe[g], esrc + g * MAXP, cnt + g,
                               lw[0][4], lw[0][5], EP(g, 0));
    }
    // layer 0 node path
    for (int g = 0; g < 2; g++) {
        k_sgemm<<<gN, 256>>>(fn[g], lw[0][0], ndx,  BN, nullptr, Hh, Hh, lw[0][1], 0, 0);
        k_sgemm<<<gN, 256>>>(fn[g], lw[0][2], ndsx, BN, nullptr, Hh, Hh, lw[0][3], 0, 0);
        k_agg<<<gA, 256>>>(EP(g, 0), rowptr + g * (BN + 1), colj + g * MAXP,
                           aval + g * MAXP, ndx, ndsx, MP(g, 0));
    }
    // edge layer 1 (relu on input)
    for (int g = 0; g < 2; g++)
        k_sgemm<<<gE, 256>>>(EP(g, 0), lw[1][4], EP(g, 1), MAXP, cnt + g, Hh, Hh, lw[1][5], 0, 1);
    // layer 1 node path
    for (int g = 0; g < 2; g++) {
        k_sgemm<<<gN, 256>>>(MP(g, 0), lw[1][0], ndx,  BN, nullptr, Hh, Hh, lw[1][1], 0, 0);
        k_sgemm<<<gN, 256>>>(MP(g, 0), lw[1][2], ndsx, BN, nullptr, Hh, Hh, lw[1][3], 0, 0);
        k_agg<<<gA, 256>>>(EP(g, 1), rowptr + g * (BN + 1), colj + g * MAXP,
                           aval + g * MAXP, ndx, ndsx, MP(g, 1));
    }
    // edge layer 2
    for (int g = 0; g < 2; g++)
        k_sgemm<<<gE, 256>>>(EP(g, 1), lw[2][4], EP(g, 0), MAXP, cnt + g, Hh, Hh, lw[2][5], 0, 1);

    // cross-graph attention after layer 1
    k_sgemm<<<gN, 256>>>(MP(0, 1), aff1, tbuf, BN, nullptr, Hh, Hh, nullptr, 0, 0);
    k_bmm_nt<<<8, 256>>>(tbuf, MP(1, 1), sraw);
    k_sinkhorn<<<8, 256>>>(sraw, ssk, n1, n2, itp);
    k_su<<<512, 256>>>(ssk, MP(1, 1), ubuf, 0);          // u1 = s @ emb2
    k_su<<<512, 256>>>(ssk, MP(0, 1), ubuf + MSZ, 1);    // u2 = s^T @ emb1
    // new_emb = emb @ W_top + u @ W_bot + cb
    k_sgemm<<<gN, 256>>>(MP(0, 1), cw,                       MP(0, 0), BN, nullptr, Hh, Hh, cb,      0, 0);
    k_sgemm<<<gN, 256>>>(ubuf,     cw + (size_t)Hh * Hh,     MP(0, 0), BN, nullptr, Hh, Hh, nullptr, 1, 0);
    k_sgemm<<<gN, 256>>>(MP(1, 1), cw,                       MP(1, 0), BN, nullptr, Hh, Hh, cb,      0, 0);
    k_sgemm<<<gN, 256>>>(ubuf + MSZ, cw + (size_t)Hh * Hh,   MP(1, 0), BN, nullptr, Hh, Hh, nullptr, 1, 0);

    // layer 2 node path
    for (int g = 0; g < 2; g++) {
        k_sgemm<<<gN, 256>>>(MP(g, 0), lw[2][0], ndx,  BN, nullptr, Hh, Hh, lw[2][1], 0, 0);
        k_sgemm<<<gN, 256>>>(MP(g, 0), lw[2][2], ndsx, BN, nullptr, Hh, Hh, lw[2][3], 0, 0);
        k_agg<<<gA, 256>>>(EP(g, 0), rowptr + g * (BN + 1), colj + g * MAXP,
                           aval + g * MAXP, ndx, ndsx, MP(g, 1));
    }
    // final affinity + sinkhorn -> output
    k_sgemm<<<gN, 256>>>(MP(0, 1), aff2, tbuf, BN, nullptr, Hh, Hh, nullptr, 0, 0);
    k_bmm_nt<<<8, 256>>>(tbuf, MP(1, 1), sraw);
    k_sinkhorn<<<8, 256>>>(sraw, out, n1, n2, itp);
#undef EP
#undef MP
}